// round 1
// baseline (speedup 1.0000x reference)
#include <cuda_runtime.h>
#include <cuda_bf16.h>
#include <math.h>

// Problem constants
#define NBATCH 256
#define LSEQ   4096
#define KERNEL 15
#define LOUT   (LSEQ - KERNEL + 1)   // 4082
#define DL     64
#define DC     128
#define NIV    (KERNEL * 4)          // 60

// Scratch: Wc[iv][c], iv = i*4+v  -> Wc[iv][c] = sum_d emb[v][d] * conv_w[c][d][i]
__device__ float g_Wc[NIV * DC];

// ---------------------------------------------------------------------------
// Kernel A: build the 15x4x128 conv-collapse table (tokens only take values 0..3)
// ---------------------------------------------------------------------------
__global__ void prep_wc_kernel(const float* __restrict__ emb,
                               const float* __restrict__ conv_w) {
    int iv = blockIdx.x;          // 0..59
    int i  = iv >> 2;
    int v  = iv & 3;
    int c  = threadIdx.x;         // 0..127
    float s = 0.f;
#pragma unroll 16
    for (int d = 0; d < DL; d++) {
        s += emb[v * DL + d] * conv_w[(c * DL + d) * KERNEL + i];
    }
    g_Wc[iv * DC + c] = s;
}

// ---------------------------------------------------------------------------
// Kernel B: one block per batch element, full fused pipeline:
//   histogram -> read_mean -> q -> qk -> S table -> scores -> softmax
//   -> weighted histogram A -> r -> out
// ---------------------------------------------------------------------------
__global__ void __launch_bounds__(256, 2)
seq_encoder_kernel(const int*   __restrict__ tokens,
                   const float* __restrict__ conv_b,
                   const float* __restrict__ Wq,
                   const float* __restrict__ bq,
                   const float* __restrict__ Wk,
                   const float* __restrict__ Wv,
                   const float* __restrict__ bv,
                   float*       __restrict__ out) {
    const int n   = blockIdx.x;
    const int tid = threadIdx.x;
    const int lane = tid & 31;
    const int warp = tid >> 5;

    __shared__ unsigned char tok_s[LSEQ];
    __shared__ float sc[LOUT];
    __shared__ float S_s[NIV];
    __shared__ float rm_s[DC];
    __shared__ float q_s[DC];
    __shared__ float qk_s[DC];
    __shared__ float r_s[DC];
    __shared__ float red_s[8];
    __shared__ float wacc[8][NIV];
    __shared__ float A_s[NIV];
    __shared__ float fcnt_s[NIV];
    __shared__ int   hist_s[4];
    __shared__ float bmax_s, bsum_s;

    if (tid < 4) hist_s[tid] = 0;
    __syncthreads();

    // ---- load tokens to shared, build full histogram ----
    const int* trow = tokens + (long)n * LSEQ;
    int c0 = 0, c1 = 0, c2 = 0, c3 = 0;
    for (int p = tid; p < LSEQ; p += 256) {
        int t = trow[p];
        tok_s[p] = (unsigned char)t;
        c0 += (t == 0); c1 += (t == 1); c2 += (t == 2); c3 += (t == 3);
    }
    c0 = __reduce_add_sync(0xffffffffu, c0);
    c1 = __reduce_add_sync(0xffffffffu, c1);
    c2 = __reduce_add_sync(0xffffffffu, c2);
    c3 = __reduce_add_sync(0xffffffffu, c3);
    if (lane == 0) {
        atomicAdd(&hist_s[0], c0);
        atomicAdd(&hist_s[1], c1);
        atomicAdd(&hist_s[2], c2);
        atomicAdd(&hist_s[3], c3);
    }
    __syncthreads();

    // ---- sliding-window counts: cnt[i][v] = #{t in [0,LOUT) : tok[t+i]==v} ----
    if (tid == 0) {
        int pre[4] = {0, 0, 0, 0};
        for (int i = 0; i < KERNEL; i++) {
            int suf[4] = {0, 0, 0, 0};
            for (int p = i + LOUT; p < LSEQ; p++) suf[tok_s[p]]++;
            for (int v = 0; v < 4; v++)
                fcnt_s[i * 4 + v] = (float)(hist_s[v] - pre[v] - suf[v]);
            pre[tok_s[i]]++;
        }
    }
    __syncthreads();

    // ---- read_mean[c] = conv_b[c] + (1/LOUT) * sum_iv cnt[iv] * Wc[iv][c] ----
    if (tid < DC) {
        float a = 0.f;
#pragma unroll
        for (int iv = 0; iv < NIV; iv++)
            a += fcnt_s[iv] * g_Wc[iv * DC + tid];
        rm_s[tid] = conv_b[tid] + a * (1.0f / (float)LOUT);
    }
    __syncthreads();

    // ---- q[c] = bq[c] + sum_d Wq[c,d] * rm[d] ----
    if (tid < DC) {
        float a = bq[tid];
        const float* wrow = Wq + tid * DC;
#pragma unroll 8
        for (int d = 0; d < DC; d++) a += wrow[d] * rm_s[d];
        q_s[tid] = a;
    }
    __syncthreads();

    // ---- qk[d] = sum_c q[c] * Wk[c,d]   (bk drops out: constant shift of scores) ----
    if (tid < DC) {
        float a = 0.f;
#pragma unroll 8
        for (int c = 0; c < DC; c++) a += q_s[c] * Wk[c * DC + tid];
        qk_s[tid] = a;
    }
    __syncthreads();

    // ---- per-batch score table S[iv] = (1/sqrt(DC)) * sum_c qk[c] * Wc[iv][c] ----
    if (tid < NIV) {
        float a = 0.f;
        const float* wrow = g_Wc + tid * DC;
#pragma unroll 8
        for (int c = 0; c < DC; c++) a += qk_s[c] * wrow[c];
        S_s[tid] = a * 0.088388347648318447f;   // 1/sqrt(128)
    }
    __syncthreads();

    // ---- scores[t] = sum_i S[i, tok[t+i]] ; track max ----
    float lmax = -1e30f;
    for (int t = tid; t < LOUT; t += 256) {
        float s = 0.f;
#pragma unroll
        for (int i = 0; i < KERNEL; i++)
            s += S_s[i * 4 + tok_s[t + i]];
        sc[t] = s;
        lmax = fmaxf(lmax, s);
    }
#pragma unroll
    for (int o = 16; o > 0; o >>= 1)
        lmax = fmaxf(lmax, __shfl_xor_sync(0xffffffffu, lmax, o));
    if (lane == 0) red_s[warp] = lmax;
    __syncthreads();
    if (tid == 0) {
        float m = red_s[0];
#pragma unroll
        for (int w = 1; w < 8; w++) m = fmaxf(m, red_s[w]);
        bmax_s = m;
    }
    __syncthreads();
    const float bmax = bmax_s;

    // ---- exp + sum ----
    float lsum = 0.f;
    for (int t = tid; t < LOUT; t += 256) {
        float e = __expf(sc[t] - bmax);
        sc[t] = e;
        lsum += e;
    }
#pragma unroll
    for (int o = 16; o > 0; o >>= 1)
        lsum += __shfl_xor_sync(0xffffffffu, lsum, o);
    if (lane == 0) red_s[warp] = lsum;
    __syncthreads();
    if (tid == 0) {
        float s = 0.f;
#pragma unroll
        for (int w = 0; w < 8; w++) s += red_s[w];
        bsum_s = s;
    }
    __syncthreads();
    const float denom = bsum_s;

    // ---- weighted histogram A[i][v] = sum_t e[t] * (tok[t+i]==v) ----
    float acc[NIV];
#pragma unroll
    for (int j = 0; j < NIV; j++) acc[j] = 0.f;
    for (int t = tid; t < LOUT; t += 256) {
        float e = sc[t];
#pragma unroll
        for (int i = 0; i < KERNEL; i++) {
            int tv = tok_s[t + i];
#pragma unroll
            for (int v = 0; v < 4; v++)
                acc[i * 4 + v] += (tv == v) ? e : 0.f;
        }
    }
#pragma unroll
    for (int j = 0; j < NIV; j++) {
#pragma unroll
        for (int o = 16; o > 0; o >>= 1)
            acc[j] += __shfl_xor_sync(0xffffffffu, acc[j], o);
    }
    if (lane == 0) {
#pragma unroll
        for (int j = 0; j < NIV; j++) wacc[warp][j] = acc[j];
    }
    __syncthreads();
    if (tid < NIV) {
        float a = 0.f;
#pragma unroll
        for (int w = 0; w < 8; w++) a += wacc[w][tid];
        A_s[tid] = a;
    }
    __syncthreads();

    // ---- r[d] = conv_b[d] + (sum_iv A[iv] * Wc[iv][d]) / denom ----
    if (tid < DC) {
        float a = 0.f;
#pragma unroll
        for (int iv = 0; iv < NIV; iv++)
            a += A_s[iv] * g_Wc[iv * DC + tid];
        r_s[tid] = conv_b[tid] + a / denom;
    }
    __syncthreads();

    // ---- out[c] = bv[c] + sum_d Wv[c,d] * r[d] ----
    if (tid < DC) {
        float a = bv[tid];
        const float* wrow = Wv + tid * DC;
#pragma unroll 8
        for (int d = 0; d < DC; d++) a += wrow[d] * r_s[d];
        out[(long)n * DC + tid] = a;
    }
}

// ---------------------------------------------------------------------------
// Launch
// Inputs (metadata order): tokens, emb, conv_w, conv_b, Wq, bq, Wk, bk, Wv, bv
// ---------------------------------------------------------------------------
extern "C" void kernel_launch(void* const* d_in, const int* in_sizes, int n_in,
                              void* d_out, int out_size) {
    const int*   tokens = (const int*)  d_in[0];
    const float* emb    = (const float*)d_in[1];
    const float* conv_w = (const float*)d_in[2];
    const float* conv_b = (const float*)d_in[3];
    const float* Wq     = (const float*)d_in[4];
    const float* bq     = (const float*)d_in[5];
    const float* Wk     = (const float*)d_in[6];
    // d_in[7] = bk  (mathematically drops out of softmax — unused)
    const float* Wv     = (const float*)d_in[8];
    const float* bv     = (const float*)d_in[9];
    float*       out    = (float*)d_out;

    prep_wc_kernel<<<NIV, DC>>>(emb, conv_w);
    seq_encoder_kernel<<<NBATCH, 256>>>(tokens, conv_b, Wq, bq, Wk, Wv, bv, out);
}

// round 2
// speedup vs baseline: 1.2444x; 1.2444x over previous
#include <cuda_runtime.h>
#include <cuda_bf16.h>

#define NBATCH 256
#define LSEQ   4096
#define KER    15
#define LOUT   (LSEQ - KER + 1)   // 4082
#define DL     64
#define DC     128
#define NIV    (KER * 4)          // 60

// ---------------- precomputed matrices (device scratch) ----------------
__device__ float g_Wc[NIV * DC];     // Wc[iv][c] = sum_d emb[v][d]*conv_w[c][d][i]
__device__ float g_M[DC * DC];       // M = Wk^T Wq
__device__ float g_mb[DC];           // mb = Wk^T bq
__device__ float g_G[NIV * DC];      // G = Wc * M
__device__ float g_P[NIV * NIV];     // P = (1/(sqrt(dc)*LOUT)) * G * Wc^T
__device__ float g_p0[NIV];          // p0 = (1/sqrt(dc)) * (Wc*mb + G*conv_b)
__device__ float g_WvWc[DC * NIV];   // WvWc[c][iv] = sum_d Wv[c][d]*Wc[iv][d]
__device__ float g_ob[DC];           // ob = bv + Wv*conv_b

// ---------------- setup kernels (tiny, run every launch) ----------------
__global__ void ka1_wc(const float* __restrict__ emb, const float* __restrict__ conv_w) {
    int iv = blockIdx.x, i = iv >> 2, v = iv & 3, c = threadIdx.x;
    float s = 0.f;
#pragma unroll 16
    for (int d = 0; d < DL; d++) s += emb[v * DL + d] * conv_w[(c * DL + d) * KER + i];
    g_Wc[iv * DC + c] = s;
}
__global__ void ka2_m(const float* __restrict__ Wq, const float* __restrict__ bq,
                      const float* __restrict__ Wk) {
    int d = blockIdx.x, e = threadIdx.x;
    float s = 0.f;
#pragma unroll 8
    for (int c = 0; c < DC; c++) s += Wk[c * DC + d] * Wq[c * DC + e];
    g_M[d * DC + e] = s;
    if (e == 0) {
        float m = 0.f;
        for (int c = 0; c < DC; c++) m += Wk[c * DC + d] * bq[c];
        g_mb[d] = m;
    }
}
__global__ void ka3_g() {
    int iv = blockIdx.x, e = threadIdx.x;
    float s = 0.f;
#pragma unroll 8
    for (int d = 0; d < DC; d++) s += g_Wc[iv * DC + d] * g_M[d * DC + e];
    g_G[iv * DC + e] = s;
}
__global__ void ka4_p(const float* __restrict__ conv_b) {
    int iv = blockIdx.x, jv = threadIdx.x;
    const float isq = 0.088388347648318447f;  // 1/sqrt(128)
    if (jv < NIV) {
        float s = 0.f;
#pragma unroll 8
        for (int e = 0; e < DC; e++) s += g_G[iv * DC + e] * g_Wc[jv * DC + e];
        g_P[iv * NIV + jv] = s * isq / (float)LOUT;
    }
    if (jv == 0) {
        float s = 0.f;
        for (int d = 0; d < DC; d++) s += g_Wc[iv * DC + d] * g_mb[d];
        for (int e = 0; e < DC; e++) s += g_G[iv * DC + e] * conv_b[e];
        g_p0[iv] = s * isq;
    }
}
__global__ void ka5_wv(const float* __restrict__ Wv, const float* __restrict__ bv,
                       const float* __restrict__ conv_b) {
    int c = blockIdx.x, jv = threadIdx.x;
    if (jv < NIV) {
        float s = 0.f;
#pragma unroll 8
        for (int d = 0; d < DC; d++) s += Wv[c * DC + d] * g_Wc[jv * DC + d];
        g_WvWc[c * NIV + jv] = s;
    }
    if (jv == 0) {
        float s = bv[c];
        for (int d = 0; d < DC; d++) s += Wv[c * DC + d] * conv_b[d];
        g_ob[c] = s;
    }
}

// ---------------- main kernel: one block per batch element ----------------
__global__ void __launch_bounds__(256, 2)
seq_main(const int* __restrict__ tokens, float* __restrict__ out) {
    __shared__ float sc[LOUT];                       // raw scores
    __shared__ unsigned long long buckets[3072];     // aliased: float Tbl[3072] in score phase
    __shared__ unsigned int Xs[129], Ys[129];        // token bitplanes (bit0 / bit1)
    __shared__ float S_s[NIV], fcnt_s[NIV], A_s[NIV];
    __shared__ float red_s[8];
    __shared__ float wacc[8][46];
    __shared__ float fin[46];                        // [0]=E, [1+i]=Ex_i, [16+i]=Ey_i, [31+i]=Exy_i
    __shared__ int hist_s[4];
    __shared__ float bmax_s;

    float* Tbl = (float*)buckets;

    const int tid = threadIdx.x, lane = tid & 31, warp = tid >> 5;
    if (tid < 4) hist_s[tid] = 0;
    if (tid == 0) { Xs[128] = 0u; Ys[128] = 0u; }
    __syncthreads();

    // ---- load tokens -> bitplanes + histogram (16 LDGs in flight, then ballots) ----
    const int* trow = tokens + (size_t)blockIdx.x * LSEQ;
    int tv[16];
#pragma unroll
    for (int m = 0; m < 16; m++) tv[m] = trow[m * 256 + warp * 32 + lane];
    int n0 = 0, n1 = 0, n2 = 0, n3 = 0;
#pragma unroll
    for (int m = 0; m < 16; m++) {
        unsigned b0 = __ballot_sync(0xffffffffu, tv[m] & 1);
        unsigned b1 = __ballot_sync(0xffffffffu, tv[m] & 2);
        if (lane == 0) {
            int w = (m * 256 + warp * 32) >> 5;
            Xs[w] = b0; Ys[w] = b1;
            int c3 = __popc(b0 & b1);
            int c1 = __popc(b0) - c3;
            int c2 = __popc(b1) - c3;
            n3 += c3; n1 += c1; n2 += c2; n0 += 32 - c1 - c2 - c3;
        }
    }
    if (lane == 0) {
        atomicAdd(&hist_s[0], n0); atomicAdd(&hist_s[1], n1);
        atomicAdd(&hist_s[2], n2); atomicAdd(&hist_s[3], n3);
    }
    __syncthreads();

#define TOK_AT(p) ((int)(((Xs[(p) >> 5] >> ((p) & 31)) & 1u) | (((Ys[(p) >> 5] >> ((p) & 31)) & 1u) << 1)))

    // ---- sliding-window counts fcnt[i][v] (parallel over 60 threads) ----
    if (tid < NIV) {
        int i = tid >> 2, v = tid & 3;
        int cnt = hist_s[v];
        for (int p = 0; p < i; p++) cnt -= (TOK_AT(p) == v);
        for (int p = i + LOUT; p < LSEQ; p++) cnt -= (TOK_AT(p) == v);
        fcnt_s[tid] = (float)cnt;
    }
    __syncthreads();

    // ---- per-batch score table S[60] = p0 + P * fcnt ----
    if (tid < NIV) {
        float s = g_p0[tid];
        const float* prow = g_P + tid * NIV;
#pragma unroll 12
        for (int j = 0; j < NIV; j++) s += prow[j] * fcnt_s[j];
        S_s[tid] = s;
    }
    __syncthreads();

    // ---- build three 1024-entry chunk tables: Tbl[k*1024+u] = sum_{j<5} S[5k+j, v_j(u)] ----
    for (int idx = tid; idx < 3072; idx += 256) {
        int k = idx >> 10, u = idx & 1023;
        int xb = u & 31, yb = u >> 5;
        float s = 0.f;
#pragma unroll
        for (int j = 0; j < 5; j++) {
            int v = ((xb >> j) & 1) | (((yb >> j) & 1) << 1);
            s += S_s[(5 * k + j) * 4 + v];
        }
        Tbl[idx] = s;
    }
    __syncthreads();

    // ---- scores + block max ----
    float lmax = -1e30f;
    for (int t = tid; t < LOUT; t += 256) {
        int wi = t >> 5, sh = t & 31;
        unsigned bx = __funnelshift_r(Xs[wi], Xs[wi + 1], sh);
        unsigned by = __funnelshift_r(Ys[wi], Ys[wi + 1], sh);
        int u0 = (bx & 31) | ((by & 31) << 5);
        int u1 = ((bx >> 5) & 31) | (((by >> 5) & 31) << 5);
        int u2 = ((bx >> 10) & 31) | (((by >> 10) & 31) << 5);
        float s = Tbl[u0] + Tbl[1024 + u1] + Tbl[2048 + u2];
        sc[t] = s;
        lmax = fmaxf(lmax, s);
    }
#pragma unroll
    for (int o = 16; o > 0; o >>= 1)
        lmax = fmaxf(lmax, __shfl_xor_sync(0xffffffffu, lmax, o));
    if (lane == 0) red_s[warp] = lmax;
    __syncthreads();                       // all Tbl reads done
    if (tid == 0) {
        float m = red_s[0];
#pragma unroll
        for (int w = 1; w < 8; w++) m = fmaxf(m, red_s[w]);
        bmax_s = m;
    }
    // zero buckets (reuses Tbl memory)
    for (int idx = tid; idx < 3072; idx += 256) buckets[idx] = 0ull;
    __syncthreads();
    const float bmax = bmax_s;

    // ---- fused exp + weighted bucket scatter (deterministic u64 fixed-point) ----
    const float SCALE = 1099511627776.0f;  // 2^40
    for (int t = tid; t < LOUT; t += 256) {
        int wi = t >> 5, sh = t & 31;
        unsigned bx = __funnelshift_r(Xs[wi], Xs[wi + 1], sh);
        unsigned by = __funnelshift_r(Ys[wi], Ys[wi + 1], sh);
        int u0 = (bx & 31) | ((by & 31) << 5);
        int u1 = ((bx >> 5) & 31) | (((by >> 5) & 31) << 5);
        int u2 = ((bx >> 10) & 31) | (((by >> 10) & 31) << 5);
        float e = __expf(sc[t] - bmax);
        unsigned long long es = (unsigned long long)(e * SCALE);
        atomicAdd(&buckets[u0], es);
        atomicAdd(&buckets[1024 + u1], es);
        atomicAdd(&buckets[2048 + u2], es);
    }
    __syncthreads();

    // ---- post-process buckets -> (E, Ex_i, Ey_i, Exy_i) ----
    float acc[46];
#pragma unroll
    for (int j = 0; j < 46; j++) acc[j] = 0.f;
    const float INV40 = 1.0f / 1099511627776.0f;
#pragma unroll
    for (int k = 0; k < 3; k++) {
        for (int m = tid; m < 1024; m += 256) {
            float val = (float)buckets[k * 1024 + m] * INV40;
            if (k == 0) acc[0] += val;
#pragma unroll
            for (int j = 0; j < 5; j++) {
                int i = 5 * k + j;
                acc[1 + i]  += ((m >> j) & 1)       ? val : 0.f;
                acc[16 + i] += ((m >> (5 + j)) & 1) ? val : 0.f;
                acc[31 + i] += (((m >> j) & (m >> (5 + j))) & 1) ? val : 0.f;
            }
        }
    }
#pragma unroll
    for (int j = 0; j < 46; j++) {
        float v = acc[j];
#pragma unroll
        for (int o = 16; o > 0; o >>= 1) v += __shfl_xor_sync(0xffffffffu, v, o);
        if (lane == 0) wacc[warp][j] = v;
    }
    __syncthreads();
    if (tid < 46) {
        float s = 0.f;
#pragma unroll
        for (int w = 0; w < 8; w++) s += wacc[w][tid];
        fin[tid] = s;
    }
    __syncthreads();

    // ---- A[i][v] from (E, Ex, Ey, Exy) ----
    if (tid < NIV) {
        int i = tid >> 2, v = tid & 3;
        float E = fin[0], Ex = fin[1 + i], Ey = fin[16 + i], Exy = fin[31 + i];
        float a = (v == 3) ? Exy
                : (v == 1) ? (Ex - Exy)
                : (v == 2) ? (Ey - Exy)
                : (E - Ex - Ey + Exy);
        A_s[tid] = a;
    }
    __syncthreads();

    // ---- out[c] = ob[c] + (WvWc * A)[c] / E ----
    if (tid < DC) {
        float s = 0.f;
        const float* wrow = g_WvWc + tid * NIV;
#pragma unroll 12
        for (int j = 0; j < NIV; j++) s += wrow[j] * A_s[j];
        out[(size_t)blockIdx.x * DC + tid] = g_ob[tid] + s / fin[0];
    }
}

// ---------------- launch ----------------
// Inputs: tokens, emb, conv_w, conv_b, Wq, bq, Wk, bk, Wv, bv  (bk drops out of softmax)
extern "C" void kernel_launch(void* const* d_in, const int* in_sizes, int n_in,
                              void* d_out, int out_size) {
    const int*   tokens = (const int*)  d_in[0];
    const float* emb    = (const float*)d_in[1];
    const float* conv_w = (const float*)d_in[2];
    const float* conv_b = (const float*)d_in[3];
    const float* Wq     = (const float*)d_in[4];
    const float* bq     = (const float*)d_in[5];
    const float* Wk     = (const float*)d_in[6];
    const float* Wv     = (const float*)d_in[8];
    const float* bv     = (const float*)d_in[9];
    float*       out    = (float*)d_out;

    ka1_wc<<<NIV, DC>>>(emb, conv_w);
    ka2_m <<<DC,  DC>>>(Wq, bq, Wk);
    ka3_g <<<NIV, DC>>>();
    ka4_p <<<NIV, 64>>>(conv_b);
    ka5_wv<<<DC,  64>>>(Wv, bv, conv_b);
    seq_main<<<NBATCH, 256>>>(tokens, out);
}

// round 3
// speedup vs baseline: 1.8014x; 1.4476x over previous
#include <cuda_runtime.h>
#include <cuda_bf16.h>

#define NBATCH 256
#define LSEQ   4096
#define KER    15
#define LOUT   (LSEQ - KER + 1)   // 4082
#define DL     64
#define DC     128
#define NIV    (KER * 4)          // 60

// ---------------- precomputed matrices (device scratch) ----------------
__device__ __align__(16) float g_Wc[NIV * DC];     // Wc[iv][c]
__device__ __align__(16) float g_U[NIV * DC];      // U = Wc * Wk^T
__device__ __align__(16) float g_V[NIV * DC];      // V = Wc * Wq^T
__device__ __align__(16) float g_P[NIV * NIV];     // P = isq/LOUT * U * V^T
__device__ __align__(16) float g_p0[NIV];          // p0 = isq * U * w
__device__ __align__(16) float g_WvWc[DC * NIV];   // Wv * Wc^T  (row c: 60 floats)
__device__ __align__(16) float g_w[DC];            // w = bq + Wq*conv_b
__device__ __align__(16) float g_ob[DC];           // ob = bv + Wv*conv_b

// ---------------- setup kernel 1: Wc ----------------
__global__ void k1_wc(const float* __restrict__ emb, const float* __restrict__ conv_w) {
    __shared__ float cw[DL * KER];   // conv_w[c][d][i], 960 floats
    __shared__ float embS[4 * DL];   // 256 floats
    const int c = blockIdx.x, tid = threadIdx.x;
    for (int idx = tid; idx < DL * KER; idx += 64) cw[idx] = conv_w[c * (DL * KER) + idx];
    for (int idx = tid; idx < 4 * DL;  idx += 64) embS[idx] = emb[idx];
    __syncthreads();
    if (tid < NIV) {
        int i = tid >> 2, v = tid & 3;
        float s = 0.f;
#pragma unroll 16
        for (int d = 0; d < DL; d++) s += embS[v * DL + d] * cw[d * KER + i];
        g_Wc[tid * DC + c] = s;
    }
}

// ---------------- setup kernel 2: U, V, WvWc, w, ob ----------------
__global__ void k2_uv(const float* __restrict__ Wq, const float* __restrict__ bq,
                      const float* __restrict__ Wk, const float* __restrict__ Wv,
                      const float* __restrict__ bv, const float* __restrict__ conv_b) {
    __shared__ float wkS[DC], wqS[DC], wvS[DC], cbS[DC];
    const int c = blockIdx.x, tid = threadIdx.x;
    for (int idx = tid; idx < DC; idx += 64) {
        wkS[idx] = Wk[c * DC + idx];
        wqS[idx] = Wq[c * DC + idx];
        wvS[idx] = Wv[c * DC + idx];
        cbS[idx] = conv_b[idx];
    }
    __syncthreads();
    if (tid < NIV) {
        const float4* wc4 = (const float4*)(g_Wc + tid * DC);
        float su = 0.f, sv = 0.f, sw = 0.f;
#pragma unroll 8
        for (int q = 0; q < DC / 4; q++) {
            float4 f = wc4[q];
            int d = q * 4;
            su += f.x * wkS[d] + f.y * wkS[d + 1] + f.z * wkS[d + 2] + f.w * wkS[d + 3];
            sv += f.x * wqS[d] + f.y * wqS[d + 1] + f.z * wqS[d + 2] + f.w * wqS[d + 3];
            sw += f.x * wvS[d] + f.y * wvS[d + 1] + f.z * wvS[d + 2] + f.w * wvS[d + 3];
        }
        g_U[tid * DC + c] = su;
        g_V[tid * DC + c] = sv;
        g_WvWc[c * NIV + tid] = sw;
    } else if (tid == 60) {
        float s = bq[c];
#pragma unroll 8
        for (int e = 0; e < DC; e++) s += wqS[e] * cbS[e];
        g_w[c] = s;
    } else if (tid == 61) {
        float s = bv[c];
#pragma unroll 8
        for (int e = 0; e < DC; e++) s += wvS[e] * cbS[e];
        g_ob[c] = s;
    }
}

// ---------------- setup kernel 3: P, p0 ----------------
__global__ void k3_p() {
    __shared__ float uS[DC];
    const int i = blockIdx.x, tid = threadIdx.x;
    const float isq = 0.088388347648318447f;  // 1/sqrt(128)
    for (int idx = tid; idx < DC; idx += 64) uS[idx] = g_U[i * DC + idx];
    __syncthreads();
    if (tid < NIV) {
        const float4* v4 = (const float4*)(g_V + tid * DC);
        float s = 0.f;
#pragma unroll 8
        for (int q = 0; q < DC / 4; q++) {
            float4 f = v4[q];
            int d = q * 4;
            s += f.x * uS[d] + f.y * uS[d + 1] + f.z * uS[d + 2] + f.w * uS[d + 3];
        }
        g_P[i * NIV + tid] = s * isq / (float)LOUT;
    } else if (tid == 60) {
        float s = 0.f;
#pragma unroll 8
        for (int d = 0; d < DC; d++) s += uS[d] * g_w[d];
        g_p0[i] = s * isq;
    }
}

// ---------------- main kernel: one block per batch element ----------------
__global__ void __launch_bounds__(256, 4)
seq_main(const int* __restrict__ tokens, float* __restrict__ out) {
    __shared__ unsigned long long buckets[3072];     // 24 KB
    __shared__ float Tbl[3072];                      // 12 KB (separate from buckets)
    __shared__ unsigned int Xs[129], Ys[129];        // token bitplanes
    __shared__ float S_s[NIV], fcnt_s[NIV], A_s[NIV];
    __shared__ float red_s[8];
    __shared__ float wacc[8][16];
    __shared__ float fin[46];     // [0]=E, [1+i]=Ex_i, [16+i]=Ey_i, [31+i]=Exy_i
    __shared__ int hist_s[4];

    const int tid = threadIdx.x, lane = tid & 31, warp = tid >> 5;

    // zero buckets up-front (no longer aliased with Tbl)
    for (int idx = tid; idx < 3072; idx += 256) buckets[idx] = 0ull;
    if (tid < 4) hist_s[tid] = 0;
    if (tid == 0) { Xs[128] = 0u; Ys[128] = 0u; }
    __syncthreads();

    // ---- tokens -> bitplanes + histogram ----
    const int* trow = tokens + (size_t)blockIdx.x * LSEQ;
    int tv[16];
#pragma unroll
    for (int m = 0; m < 16; m++) tv[m] = trow[m * 256 + warp * 32 + lane];
    int n0 = 0, n1 = 0, n2 = 0, n3 = 0;
#pragma unroll
    for (int m = 0; m < 16; m++) {
        unsigned b0 = __ballot_sync(0xffffffffu, tv[m] & 1);
        unsigned b1 = __ballot_sync(0xffffffffu, tv[m] & 2);
        if (lane == 0) {
            int w = (m * 256 + warp * 32) >> 5;
            Xs[w] = b0; Ys[w] = b1;
            int c3 = __popc(b0 & b1);
            int c1 = __popc(b0) - c3;
            int c2 = __popc(b1) - c3;
            n3 += c3; n1 += c1; n2 += c2; n0 += 32 - c1 - c2 - c3;
        }
    }
    if (lane == 0) {
        atomicAdd(&hist_s[0], n0); atomicAdd(&hist_s[1], n1);
        atomicAdd(&hist_s[2], n2); atomicAdd(&hist_s[3], n3);
    }
    __syncthreads();

#define TOK_AT(p) ((int)(((Xs[(p) >> 5] >> ((p) & 31)) & 1u) | (((Ys[(p) >> 5] >> ((p) & 31)) & 1u) << 1)))

    // ---- sliding-window counts ----
    if (tid < NIV) {
        int i = tid >> 2, v = tid & 3;
        int cnt = hist_s[v];
        for (int p = 0; p < i; p++) cnt -= (TOK_AT(p) == v);
        for (int p = i + LOUT; p < LSEQ; p++) cnt -= (TOK_AT(p) == v);
        fcnt_s[tid] = (float)cnt;
    }
    __syncthreads();

    // ---- S[60] = p0 + P*fcnt (row stride 240B, float4-aligned) ----
    if (tid < NIV) {
        float s = g_p0[tid];
        const float4* p4 = (const float4*)(g_P + tid * NIV);
#pragma unroll
        for (int q = 0; q < NIV / 4; q++) {
            float4 f = p4[q];
            int j = q * 4;
            s += f.x * fcnt_s[j] + f.y * fcnt_s[j + 1] + f.z * fcnt_s[j + 2] + f.w * fcnt_s[j + 3];
        }
        S_s[tid] = s;
    }
    __syncthreads();

    // ---- chunk tables ----
    for (int idx = tid; idx < 3072; idx += 256) {
        int k = idx >> 10, u = idx & 1023;
        int xb = u & 31, yb = u >> 5;
        float s = 0.f;
#pragma unroll
        for (int j = 0; j < 5; j++) {
            int v = ((xb >> j) & 1) | (((yb >> j) & 1) << 1);
            s += S_s[(5 * k + j) * 4 + v];
        }
        Tbl[idx] = s;
    }
    __syncthreads();

    // ---- pass 1: block max (no score store) ----
    float lmax = -1e30f;
    for (int t = tid; t < LOUT; t += 256) {
        int wi = t >> 5, sh = t & 31;
        unsigned bx = __funnelshift_r(Xs[wi], Xs[wi + 1], sh);
        unsigned by = __funnelshift_r(Ys[wi], Ys[wi + 1], sh);
        int u0 = (bx & 31) | ((by & 31) << 5);
        int u1 = ((bx >> 5) & 31) | (((by >> 5) & 31) << 5);
        int u2 = ((bx >> 10) & 31) | (((by >> 10) & 31) << 5);
        lmax = fmaxf(lmax, Tbl[u0] + Tbl[1024 + u1] + Tbl[2048 + u2]);
    }
#pragma unroll
    for (int o = 16; o > 0; o >>= 1)
        lmax = fmaxf(lmax, __shfl_xor_sync(0xffffffffu, lmax, o));
    if (lane == 0) red_s[warp] = lmax;
    __syncthreads();
    float bmax = red_s[0];
#pragma unroll
    for (int w = 1; w < 8; w++) bmax = fmaxf(bmax, red_s[w]);

    // ---- pass 2: exp + deterministic fixed-point scatter ----
    const float SCALE = 1099511627776.0f;  // 2^40
    for (int t = tid; t < LOUT; t += 256) {
        int wi = t >> 5, sh = t & 31;
        unsigned bx = __funnelshift_r(Xs[wi], Xs[wi + 1], sh);
        unsigned by = __funnelshift_r(Ys[wi], Ys[wi + 1], sh);
        int u0 = (bx & 31) | ((by & 31) << 5);
        int u1 = ((bx >> 5) & 31) | (((by >> 5) & 31) << 5);
        int u2 = ((bx >> 10) & 31) | (((by >> 10) & 31) << 5);
        float e = __expf(Tbl[u0] + Tbl[1024 + u1] + Tbl[2048 + u2] - bmax);
        unsigned long long es = (unsigned long long)(e * SCALE);
        atomicAdd(&buckets[u0], es);
        atomicAdd(&buckets[1024 + u1], es);
        atomicAdd(&buckets[2048 + u2], es);
    }
    __syncthreads();

    // ---- post-process buckets chunk-by-chunk (acc[15]+E, low reg pressure) ----
    const float INV40 = 1.0f / 1099511627776.0f;
    for (int k = 0; k < 3; k++) {
        float acc[15];
#pragma unroll
        for (int j = 0; j < 15; j++) acc[j] = 0.f;
        float accE = 0.f;
        for (int m = tid; m < 1024; m += 256) {
            float val = (float)buckets[k * 1024 + m] * INV40;
            accE += val;
#pragma unroll
            for (int j = 0; j < 5; j++) {
                acc[j]      += ((m >> j) & 1)       ? val : 0.f;
                acc[5 + j]  += ((m >> (5 + j)) & 1) ? val : 0.f;
                acc[10 + j] += (((m >> j) & (m >> (5 + j))) & 1) ? val : 0.f;
            }
        }
#pragma unroll
        for (int j = 0; j < 15; j++) {
            float v = acc[j];
#pragma unroll
            for (int o = 16; o > 0; o >>= 1) v += __shfl_xor_sync(0xffffffffu, v, o);
            if (lane == 0) wacc[warp][j] = v;
        }
        if (k == 0) {
#pragma unroll
            for (int o = 16; o > 0; o >>= 1) accE += __shfl_xor_sync(0xffffffffu, accE, o);
            if (lane == 0) wacc[warp][15] = accE;
        }
        __syncthreads();
        if (tid < 16 && (tid < 15 || k == 0)) {
            float s = 0.f;
#pragma unroll
            for (int w = 0; w < 8; w++) s += wacc[w][tid];
            if (tid == 15) fin[0] = s;
            else {
                int jj = tid % 5, i = 5 * k + jj;
                int dest = (tid < 5) ? (1 + i) : (tid < 10) ? (16 + i) : (31 + i);
                fin[dest] = s;
            }
        }
        __syncthreads();
    }

    // ---- A[i][v] ----
    if (tid < NIV) {
        int i = tid >> 2, v = tid & 3;
        float E = fin[0], Ex = fin[1 + i], Ey = fin[16 + i], Exy = fin[31 + i];
        A_s[tid] = (v == 3) ? Exy
                 : (v == 1) ? (Ex - Exy)
                 : (v == 2) ? (Ey - Exy)
                 : (E - Ex - Ey + Exy);
    }
    __syncthreads();

    // ---- out[c] = ob[c] + (WvWc*A)[c]/E ----
    if (tid < DC) {
        const float4* w4 = (const float4*)(g_WvWc + tid * NIV);
        float s = 0.f;
#pragma unroll
        for (int q = 0; q < NIV / 4; q++) {
            float4 f = w4[q];
            int j = q * 4;
            s += f.x * A_s[j] + f.y * A_s[j + 1] + f.z * A_s[j + 2] + f.w * A_s[j + 3];
        }
        out[(size_t)blockIdx.x * DC + tid] = g_ob[tid] + s / fin[0];
    }
}

// ---------------- launch ----------------
// Inputs: tokens, emb, conv_w, conv_b, Wq, bq, Wk, bk, Wv, bv  (bk drops out of softmax)
extern "C" void kernel_launch(void* const* d_in, const int* in_sizes, int n_in,
                              void* d_out, int out_size) {
    const int*   tokens = (const int*)  d_in[0];
    const float* emb    = (const float*)d_in[1];
    const float* conv_w = (const float*)d_in[2];
    const float* conv_b = (const float*)d_in[3];
    const float* Wq     = (const float*)d_in[4];
    const float* bq     = (const float*)d_in[5];
    const float* Wk     = (const float*)d_in[6];
    const float* Wv     = (const float*)d_in[8];
    const float* bv     = (const float*)d_in[9];
    float*       out    = (float*)d_out;

    k1_wc<<<DC, 64>>>(emb, conv_w);
    k2_uv<<<DC, 64>>>(Wq, bq, Wk, Wv, bv, conv_b);
    k3_p <<<NIV, 64>>>();
    seq_main<<<NBATCH, 256>>>(tokens, out);
}